// round 2
// baseline (speedup 1.0000x reference)
#include <cuda_runtime.h>
#include <cuda_bf16.h>

// VectorQuantizer on GB300 — bit-exact emulation of reference fp32 arithmetic.
// z: (64,128,64,64) f32 NCHW, emb: (256,128) f32.
// Outputs flattened f32: [quantized_ste (33554432)] [idx (262144)] [commit] [codebook]

#define C_DIM   128
#define K_CODES 256
#define HW      4096
#define N_TOT   262144
#define BN      64
#define NTH     256
#define NQ      33554432

// smem layout (floats)
#define E_OFF    0                       // embT [c][k]: 32768 floats
#define Z2_OFF   32768                   // z dup [c][n] float2: 16384 floats
#define SE_OFF   (Z2_OFF + 16384)        // 256
#define A_OFF    (SE_OFF + 256)          // 64
#define IDX_OFF  (A_OFF + 64)            // 64 (ints)
#define WS_OFF   (IDX_OFF + 64)          // 8
#define SMEM_FLOATS (WS_OFF + 8)
#define SMEM_BYTES  (SMEM_FLOATS * 4)    // ~198 KB

__device__ float  d_embT[C_DIM * K_CODES];  // [c][k]
__device__ float  d_se[K_CODES];
__device__ double d_loss_sum;

// ---------------------------------------------------------------------------
__global__ void vq_prep(const float* __restrict__ emb) {
    int t = threadIdx.x;  // 256
    if (t == 0) d_loss_sum = 0.0;
    {   // ||e_k||^2, sequential fused fma (order negligible at this scale)
        const float* row = emb + t * C_DIM;
        float s = 0.f;
        for (int c = 0; c < C_DIM; ++c) s = fmaf(row[c], row[c], s);
        d_se[t] = s;
    }
    for (int idx = t; idx < K_CODES * C_DIM; idx += NTH) {
        int k = idx >> 7, c = idx & 127;
        d_embT[c * K_CODES + k] = emb[idx];
    }
}

// two independent IEEE-RN fma chains per instruction (lanes = adjacent k)
#define FMA2(d, a, b) asm("fma.rn.f32x2 %0, %1, %2, %0;" : "+l"(d) : "l"(a), "l"(b))

// ---------------------------------------------------------------------------
__global__ void __launch_bounds__(NTH, 1)
vq_main(const float* __restrict__ z, float* __restrict__ out_q,
        float* __restrict__ out_idx) {
    extern __shared__ float smem[];
    float* e_s  = smem + E_OFF;    // [c][k]
    float* z2   = smem + Z2_OFF;   // [c][n] duplicated float2
    float* se_s = smem + SE_OFF;
    float* A_s  = smem + A_OFF;
    int*   idx_s = (int*)(smem + IDX_OFF);
    float* wsum  = smem + WS_OFF;

    const int tid    = threadIdx.x;
    const int base_n = blockIdx.x * BN;
    const int b      = base_n >> 12;       // /HW
    const int hw0    = base_n & 4095;
    const float* zb  = z + (size_t)b * (C_DIM * HW) + hw0;

    // ---- phase 1: z tile -> duplicated smem; se copy ----
    #pragma unroll
    for (int i = 0; i < 8; ++i) {
        int idx = tid + i * NTH;           // 2048 float4
        int c   = idx >> 4;
        int n4  = (idx & 15) << 2;
        float4 v = *(const float4*)(zb + (size_t)c * HW + n4);
        float2* dst = (float2*)z2 + c * 64 + n4;
        dst[0] = make_float2(v.x, v.x);
        dst[1] = make_float2(v.y, v.y);
        dst[2] = make_float2(v.z, v.z);
        dst[3] = make_float2(v.w, v.w);
    }
    se_s[tid] = d_se[tid];
    __syncthreads();

    // ---- phase 2: A_n (any fp32 fused-fma order: argmin-invariant) | embT copy ----
    if (tid < 64) {
        float a = 0.f;
        const float* zp = z2 + tid * 2;    // z2[c][tid].x, stride 128 floats
        #pragma unroll 8
        for (int c = 0; c < C_DIM; ++c) {
            float v = zp[c * 128];
            a = fmaf(v, v, a);
        }
        A_s[tid] = a;
    } else {
        const float4* src = (const float4*)d_embT;
        float4* dst = (float4*)e_s;
        for (int i = tid - 64; i < 8192; i += 192) dst[i] = src[i];
    }
    __syncthreads();

    // ---- mainloop: G[n,k] = sequential fused-fma chain over c = 0..127 ----
    const int nG = tid >> 5;               // 8 groups of 8 n
    const int kG = tid & 31;               // 32 groups of 8 k
    const int n0 = nG * 8;
    const int k0 = kG * 8;

    unsigned long long acc[8][4];
    #pragma unroll
    for (int i = 0; i < 8; ++i)
        #pragma unroll
        for (int j = 0; j < 4; ++j) acc[i][j] = 0ULL;

    #pragma unroll 4
    for (int c = 0; c < C_DIM; ++c) {
        const ulonglong2* zp = (const ulonglong2*)((const float2*)z2 + c * 64 + n0);
        ulonglong2 za0 = zp[0], za1 = zp[1], za2 = zp[2], za3 = zp[3]; // warp-broadcast
        const ulonglong2* ep = (const ulonglong2*)(e_s + c * K_CODES + k0);
        ulonglong2 eb0 = ep[0], eb1 = ep[1];
        unsigned long long A8[8] = {za0.x, za0.y, za1.x, za1.y,
                                    za2.x, za2.y, za3.x, za3.y};
        unsigned long long B4[4] = {eb0.x, eb0.y, eb1.x, eb1.y};
        #pragma unroll
        for (int i = 0; i < 8; ++i)
            #pragma unroll
            for (int j = 0; j < 4; ++j) FMA2(acc[i][j], A8[i], B4[j]);
    }

    // ---- argmin: d = RN(RN(A - 2G) + se_k), first-index tie-break ----
    #pragma unroll
    for (int i = 0; i < 8; ++i) {
        float An = A_s[n0 + i];
        unsigned long long best = 0ULL;
        #pragma unroll
        for (int j = 0; j < 4; ++j) {
            float2 g = *(float2*)&acc[i][j];
            int ka = k0 + 2 * j, kb = ka + 1;
            float ua = __fadd_rn(An, -__fmul_rn(2.0f, g.x));
            float da = __fadd_rn(ua, se_s[ka]);
            float ub = __fadd_rn(An, -__fmul_rn(2.0f, g.y));
            float db = __fadd_rn(ub, se_s[kb]);
            unsigned va = __float_as_uint(da);
            va = ((int)va < 0) ? ~va : (va | 0x80000000u);
            unsigned vb = __float_as_uint(db);
            vb = ((int)vb < 0) ? ~vb : (vb | 0x80000000u);
            unsigned long long keya = ((unsigned long long)(~va) << 32) | (unsigned)(255 - ka);
            unsigned long long keyb = ((unsigned long long)(~vb) << 32) | (unsigned)(255 - kb);
            if (keya > best) best = keya;
            if (keyb > best) best = keyb;
        }
        #pragma unroll
        for (int off = 16; off > 0; off >>= 1) {
            unsigned long long o = __shfl_xor_sync(0xFFFFFFFFu, best, off);
            if (o > best) best = o;
        }
        if (kG == 0) idx_s[n0 + i] = 255 - (int)(best & 0xFFFFFFFFull);
    }
    __syncthreads();

    // ---- output: q_ste = RN(z + RN(q - z));  loss += RN(q-z)^2 ----
    float* outb = out_q + (size_t)b * (C_DIM * HW) + hw0;
    float lsum = 0.f;
    #pragma unroll
    for (int i = 0; i < 32; ++i) {
        int flat = tid + i * NTH;          // 8192
        int c = flat >> 6;
        int n = flat & 63;
        int k = idx_s[n];
        float q  = e_s[c * K_CODES + k];
        float zv = z2[(c * 64 + n) * 2];
        float dq = q - zv;
        lsum = fmaf(dq, dq, lsum);
        outb[(size_t)c * HW + n] = zv + dq;
    }
    if (out_idx != nullptr && tid < 64)
        out_idx[base_n + tid] = (float)idx_s[tid];

    #pragma unroll
    for (int off = 16; off > 0; off >>= 1)
        lsum += __shfl_xor_sync(0xFFFFFFFFu, lsum, off);
    if ((tid & 31) == 0) wsum[tid >> 5] = lsum;
    __syncthreads();
    if (tid == 0) {
        float t = 0.f;
        #pragma unroll
        for (int w = 0; w < 8; ++w) t += wsum[w];
        atomicAdd(&d_loss_sum, (double)t);
    }
}

__global__ void vq_finalize(float* out_s) {
    double mse = d_loss_sum * (1.0 / (double)NQ);
    out_s[0] = (float)(0.25 * mse);
    out_s[1] = (float)mse;
}

extern "C" void kernel_launch(void* const* d_in, const int* in_sizes, int n_in,
                              void* d_out, int out_size) {
    const float *z, *emb;
    if (n_in >= 2 && in_sizes[0] == K_CODES * C_DIM) {
        emb = (const float*)d_in[0];
        z   = (const float*)d_in[1];
    } else {
        z   = (const float*)d_in[0];
        emb = (const float*)d_in[1];
    }
    float* out = (float*)d_out;

    cudaFuncSetAttribute(vq_main, cudaFuncAttributeMaxDynamicSharedMemorySize,
                         SMEM_BYTES);

    float* out_idx = nullptr;
    float* out_s   = nullptr;
    long long osz = (long long)out_size;
    if (osz >= (long long)NQ + N_TOT)     out_idx = out + NQ;
    if (osz >= (long long)NQ + N_TOT + 2) out_s   = out + NQ + N_TOT;

    vq_prep<<<1, NTH>>>(emb);
    vq_main<<<N_TOT / BN, NTH, SMEM_BYTES>>>(z, out, out_idx);
    if (out_s) vq_finalize<<<1, 1>>>(out_s);
}

// round 3
// speedup vs baseline: 1.4328x; 1.4328x over previous
#include <cuda_runtime.h>
#include <cuda_bf16.h>

// VectorQuantizer on GB300 — bit-exact emulation of reference fp32 arithmetic.
// Persistent-CTA GEMM + argmin + gather + loss. z:(64,128,64,64) f32, emb:(256,128) f32.
// Out f32: [quantized_ste 33554432][idx 262144][commit][codebook]

#define C_DIM   128
#define K_CODES 256
#define HW      4096
#define N_TOT   262144
#define BN      64
#define N_TILES (N_TOT / BN)     // 4096
#define NTH     256
#define NQ      33554432
#define GRID    148

// smem layout (floats)
#define E_OFF    0                        // embT [c][k] 32768
#define ZB_OFF   32768                    // 2 x 8192 raw z [buf][c][n]
#define SE_OFF   (ZB_OFF + 16384)         // 256
#define AP_OFF   (SE_OFF + 256)           // 256 partials
#define A_OFF    (AP_OFF + 256)           // 64
#define IDX_OFF  (A_OFF + 64)             // 64 ints
#define WS_OFF   (IDX_OFF + 64)           // 8
#define SMEM_FLOATS (WS_OFF + 8)
#define SMEM_BYTES  (SMEM_FLOATS * 4)     // ~199 KB

__device__ float  d_embT[C_DIM * K_CODES];   // [c][k]
__device__ float  d_se[K_CODES];
__device__ double d_loss_sum;

// ---------------------------------------------------------------------------
__global__ void vq_prep(const float* __restrict__ emb) {
    int t = threadIdx.x, b = blockIdx.x;            // 64 x 256
    if (b == 0 && t == 0) d_loss_sum = 0.0;
    if (b == 0) {   // ||e_k||^2 : sequential fused-fma, one code per thread
        const float* row = emb + t * C_DIM;
        float s = 0.f;
        for (int c = 0; c < C_DIM; ++c) s = fmaf(row[c], row[c], s);
        d_se[t] = s;
    }
    int base = b * 512;                              // 32768 / 64 blocks
    #pragma unroll
    for (int i = 0; i < 2; ++i) {
        int idx = base + t + i * NTH;
        int k = idx >> 7, c = idx & 127;
        d_embT[c * K_CODES + k] = emb[idx];
    }
}

// two independent IEEE-RN fma chains per instruction (lanes = adjacent k)
#define FMA2(d, a, b) asm("fma.rn.f32x2 %0, %1, %2, %0;" : "+l"(d) : "l"(a), "l"(b))

__device__ __forceinline__ unsigned long long dup2(float x) {
    unsigned long long r;
    unsigned u = __float_as_uint(x);
    asm("mov.b64 %0, {%1, %1};" : "=l"(r) : "r"(u));
    return r;
}

__device__ __forceinline__ void cp16(float* dst_smem, const float* src) {
    unsigned d = (unsigned)__cvta_generic_to_shared(dst_smem);
    asm volatile("cp.async.cg.shared.global [%0], [%1], 16;" :: "r"(d), "l"(src));
}
#define CP_COMMIT() asm volatile("cp.async.commit_group;")
#define CP_WAIT0()  asm volatile("cp.async.wait_group 0;")

// ---------------------------------------------------------------------------
__global__ void __launch_bounds__(NTH, 1)
vq_main(const float* __restrict__ z, float* __restrict__ out_q,
        float* __restrict__ out_idx) {
    extern __shared__ float smem[];
    float* e_s   = smem + E_OFF;
    float* zbuf0 = smem + ZB_OFF;
    float* zbuf1 = smem + ZB_OFF + 8192;
    float* se_s  = smem + SE_OFF;
    float* Ap    = smem + AP_OFF;
    float* A_s   = smem + A_OFF;
    int*   idx_s = (int*)(smem + IDX_OFF);
    float* wsum  = smem + WS_OFF;

    const int tid = threadIdx.x;

    // ---- load codebook once (L2-broadcast across the 148 CTAs) + se ----
    {
        const float4* src = (const float4*)d_embT;
        float4* dst = (float4*)e_s;
        #pragma unroll
        for (int i = 0; i < 32; ++i) dst[tid + i * NTH] = src[tid + i * NTH];
    }
    se_s[tid] = d_se[tid];

    const int nG = tid >> 5, kG = tid & 31;
    const int n0 = nG * 8, k0 = kG * 8;
    float lsum_tot = 0.f;

    // ---- prefetch first tile ----
    int tile = blockIdx.x;
    {
        int b = tile >> 6, hw0 = (tile & 63) << 6;
        const float* zb = z + (size_t)b * (C_DIM * HW) + hw0;
        #pragma unroll
        for (int i = 0; i < 8; ++i) {
            int idx = tid + i * NTH;
            int c = idx >> 4, n4 = (idx & 15) << 2;
            cp16(zbuf0 + c * 64 + n4, zb + (size_t)c * HW + n4);
        }
        CP_COMMIT();
    }

    int buf = 0;
    for (; tile < N_TILES; tile += GRID) {
        float* zcur = buf ? zbuf1 : zbuf0;
        float* znxt = buf ? zbuf0 : zbuf1;

        CP_WAIT0();
        __syncthreads();

        int next = tile + GRID;
        if (next < N_TILES) {
            int b = next >> 6, hw0 = (next & 63) << 6;
            const float* zb = z + (size_t)b * (C_DIM * HW) + hw0;
            #pragma unroll
            for (int i = 0; i < 8; ++i) {
                int idx = tid + i * NTH;
                int c = idx >> 4, n4 = (idx & 15) << 2;
                cp16(znxt + c * 64 + n4, zb + (size_t)c * HW + n4);
            }
            CP_COMMIT();
        }

        // ---- A_n via 4 partial fused-fma chains (argmin-invariant order) ----
        {
            int n = tid & 63, part = tid >> 6;
            const float* zp = zcur + part * 32 * 64 + n;
            float a = 0.f;
            #pragma unroll 8
            for (int c = 0; c < 32; ++c) { float v = zp[c * 64]; a = fmaf(v, v, a); }
            Ap[tid] = a;
        }
        __syncthreads();
        if (tid < 64)
            A_s[tid] = ((Ap[tid] + Ap[64 + tid]) + Ap[128 + tid]) + Ap[192 + tid];
        __syncthreads();

        // ---- mainloop: G[n,k] sequential fused-fma over c = 0..127 ----
        unsigned long long acc[8][4];
        #pragma unroll
        for (int i = 0; i < 8; ++i)
            #pragma unroll
            for (int j = 0; j < 4; ++j) acc[i][j] = 0ULL;

        #pragma unroll 4
        for (int c = 0; c < C_DIM; ++c) {
            const float2* zp = (const float2*)(zcur + c * 64) + (n0 >> 1);
            float2 p0 = zp[0], p1 = zp[1], p2 = zp[2], p3 = zp[3];  // warp-broadcast
            const ulonglong2* ep = (const ulonglong2*)(e_s + c * K_CODES + k0);
            ulonglong2 e0 = ep[0], e1 = ep[1];
            unsigned long long A8[8] = {dup2(p0.x), dup2(p0.y), dup2(p1.x), dup2(p1.y),
                                        dup2(p2.x), dup2(p2.y), dup2(p3.x), dup2(p3.y)};
            unsigned long long B4[4] = {e0.x, e0.y, e1.x, e1.y};
            #pragma unroll
            for (int i = 0; i < 8; ++i)
                #pragma unroll
                for (int j = 0; j < 4; ++j) FMA2(acc[i][j], A8[i], B4[j]);
        }

        // ---- argmin: d = RN(RN(A - 2G) + se_k), first-index tie-break ----
        #pragma unroll
        for (int i = 0; i < 8; ++i) {
            float An = A_s[n0 + i];
            unsigned long long best = 0ULL;
            #pragma unroll
            for (int j = 0; j < 4; ++j) {
                float2 g = *(float2*)&acc[i][j];
                int ka = k0 + 2 * j, kb = ka + 1;
                float da = __fadd_rn(__fadd_rn(An, -__fmul_rn(2.0f, g.x)), se_s[ka]);
                float db = __fadd_rn(__fadd_rn(An, -__fmul_rn(2.0f, g.y)), se_s[kb]);
                unsigned va = __float_as_uint(da);
                va = ((int)va < 0) ? ~va : (va | 0x80000000u);
                unsigned vb = __float_as_uint(db);
                vb = ((int)vb < 0) ? ~vb : (vb | 0x80000000u);
                unsigned long long keya = ((unsigned long long)(~va) << 32) | (unsigned)(255 - ka);
                unsigned long long keyb = ((unsigned long long)(~vb) << 32) | (unsigned)(255 - kb);
                if (keya > best) best = keya;
                if (keyb > best) best = keyb;
            }
            #pragma unroll
            for (int off = 16; off > 0; off >>= 1) {
                unsigned long long o = __shfl_xor_sync(0xFFFFFFFFu, best, off);
                if (o > best) best = o;
            }
            if (kG == 0) idx_s[n0 + i] = 255 - (int)(best & 0xFFFFFFFFull);
        }
        __syncthreads();

        // ---- epilogue: q_ste = RN(z + RN(q-z)); loss += RN(q-z)^2 ----
        {
            int b = tile >> 6, hw0 = (tile & 63) << 6;
            float* outb = out_q + (size_t)b * (C_DIM * HW) + hw0;
            #pragma unroll
            for (int i = 0; i < 8; ++i) {
                int idx = tid + i * NTH;           // 2048 float4
                int c = idx >> 4, n4 = (idx & 15) << 2;
                float4 zv = *(const float4*)(zcur + c * 64 + n4);
                int ka = idx_s[n4], kb = idx_s[n4 + 1], kc = idx_s[n4 + 2], kd = idx_s[n4 + 3];
                const float* ec = e_s + c * K_CODES;
                float d0 = ec[ka] - zv.x, d1 = ec[kb] - zv.y;
                float d2 = ec[kc] - zv.z, d3 = ec[kd] - zv.w;
                lsum_tot = fmaf(d0, d0, lsum_tot);
                lsum_tot = fmaf(d1, d1, lsum_tot);
                lsum_tot = fmaf(d2, d2, lsum_tot);
                lsum_tot = fmaf(d3, d3, lsum_tot);
                float4 o = make_float4(zv.x + d0, zv.y + d1, zv.z + d2, zv.w + d3);
                *(float4*)(outb + (size_t)c * HW + n4) = o;
            }
            if (out_idx != nullptr && tid < 64)
                out_idx[(size_t)tile * BN + tid] = (float)idx_s[tid];
        }
        buf ^= 1;
    }

    // ---- one loss reduction per block ----
    #pragma unroll
    for (int off = 16; off > 0; off >>= 1)
        lsum_tot += __shfl_xor_sync(0xFFFFFFFFu, lsum_tot, off);
    if ((tid & 31) == 0) wsum[tid >> 5] = lsum_tot;
    __syncthreads();
    if (tid == 0) {
        float t = 0.f;
        #pragma unroll
        for (int w = 0; w < 8; ++w) t += wsum[w];
        atomicAdd(&d_loss_sum, (double)t);
    }
}

__global__ void vq_finalize(float* out_s) {
    double mse = d_loss_sum * (1.0 / (double)NQ);
    out_s[0] = (float)(0.25 * mse);
    out_s[1] = (float)mse;
}

extern "C" void kernel_launch(void* const* d_in, const int* in_sizes, int n_in,
                              void* d_out, int out_size) {
    const float *z, *emb;
    if (n_in >= 2 && in_sizes[0] == K_CODES * C_DIM) {
        emb = (const float*)d_in[0];
        z   = (const float*)d_in[1];
    } else {
        z   = (const float*)d_in[0];
        emb = (const float*)d_in[1];
    }
    float* out = (float*)d_out;

    cudaFuncSetAttribute(vq_main, cudaFuncAttributeMaxDynamicSharedMemorySize,
                         SMEM_BYTES);

    float* out_idx = nullptr;
    float* out_s   = nullptr;
    long long osz = (long long)out_size;
    if (osz >= (long long)NQ + N_TOT)     out_idx = out + NQ;
    if (osz >= (long long)NQ + N_TOT + 2) out_s   = out + NQ + N_TOT;

    vq_prep<<<64, NTH>>>(emb);
    vq_main<<<GRID, NTH, SMEM_BYTES>>>(z, out, out_idx);
    if (out_s) vq_finalize<<<1, 1>>>(out_s);
}

// round 4
// speedup vs baseline: 1.4334x; 1.0004x over previous
#include <cuda_runtime.h>
#include <cuda_bf16.h>

// VectorQuantizer on GB300 — bit-exact emulation of reference fp32 arithmetic.
// Persistent-CTA GEMM + argmin + gather + loss. z:(64,128,64,64) f32, emb:(256,128) f32.
// Out f32: [quantized_ste 33554432][idx 262144][commit][codebook]

#define C_DIM   128
#define K_CODES 256
#define HW      4096
#define N_TOT   262144
#define BN      64
#define N_TILES (N_TOT / BN)     // 4096
#define NTH     256
#define NQ      33554432
#define GRID    148

// smem layout (floats)
#define E_OFF    0                        // embT [c][k] 32768
#define ZB_OFF   32768                    // 2 x 8192 raw z [buf][c][n]
#define SE_OFF   (ZB_OFF + 16384)         // 256
#define AP_OFF   (SE_OFF + 256)           // 256 partials
#define A_OFF    (AP_OFF + 256)           // 64
#define IDX_OFF  (A_OFF + 64)             // 64 ints
#define WS_OFF   (IDX_OFF + 64)           // 8
#define SMEM_FLOATS (WS_OFF + 8)
#define SMEM_BYTES  (SMEM_FLOATS * 4)     // ~199 KB

__device__ float  d_embT[C_DIM * K_CODES];   // [c][k]
__device__ float  d_se[K_CODES];
__device__ double d_loss_sum;

// ---------------------------------------------------------------------------
__global__ void vq_prep(const float* __restrict__ emb) {
    int t = threadIdx.x, b = blockIdx.x;            // 64 x 256
    if (b == 0 && t == 0) d_loss_sum = 0.0;
    if (b == 0) {   // ||e_k||^2 : sequential fused-fma, one code per thread
        const float* row = emb + t * C_DIM;
        float s = 0.f;
        for (int c = 0; c < C_DIM; ++c) s = fmaf(row[c], row[c], s);
        d_se[t] = s;
    }
    int base = b * 512;                              // 32768 / 64 blocks
    #pragma unroll
    for (int i = 0; i < 2; ++i) {
        int idx = base + t + i * NTH;
        int k = idx >> 7, c = idx & 127;
        d_embT[c * K_CODES + k] = emb[idx];
    }
}

// two independent IEEE-RN fma chains per instruction (lanes = adjacent k)
#define FMA2(d, a, b) asm("fma.rn.f32x2 %0, %1, %2, %0;" : "+l"(d) : "l"(a), "l"(b))

__device__ __forceinline__ unsigned long long dup2(float x) {
    unsigned long long r;
    unsigned u = __float_as_uint(x);
    asm("mov.b64 %0, {%1, %1};" : "=l"(r) : "r"(u));
    return r;
}

__device__ __forceinline__ void cp16(float* dst_smem, const float* src) {
    unsigned d = (unsigned)__cvta_generic_to_shared(dst_smem);
    asm volatile("cp.async.cg.shared.global [%0], [%1], 16;" :: "r"(d), "l"(src));
}
#define CP_COMMIT() asm volatile("cp.async.commit_group;")
#define CP_WAIT0()  asm volatile("cp.async.wait_group 0;")

// ---------------------------------------------------------------------------
__global__ void __launch_bounds__(NTH, 1)
vq_main(const float* __restrict__ z, float* __restrict__ out_q,
        float* __restrict__ out_idx) {
    extern __shared__ float smem[];
    float* e_s   = smem + E_OFF;
    float* zbuf0 = smem + ZB_OFF;
    float* zbuf1 = smem + ZB_OFF + 8192;
    float* se_s  = smem + SE_OFF;
    float* Ap    = smem + AP_OFF;
    float* A_s   = smem + A_OFF;
    int*   idx_s = (int*)(smem + IDX_OFF);
    float* wsum  = smem + WS_OFF;

    const int tid = threadIdx.x;

    // ---- load codebook once (L2-broadcast across the 148 CTAs) + se ----
    {
        const float4* src = (const float4*)d_embT;
        float4* dst = (float4*)e_s;
        #pragma unroll
        for (int i = 0; i < 32; ++i) dst[tid + i * NTH] = src[tid + i * NTH];
    }
    se_s[tid] = d_se[tid];

    const int nG = tid >> 5, kG = tid & 31;
    const int n0 = nG * 8, k0 = kG * 8;
    float lsum_tot = 0.f;

    // ---- prefetch first tile ----
    int tile = blockIdx.x;
    {
        int b = tile >> 6, hw0 = (tile & 63) << 6;
        const float* zb = z + (size_t)b * (C_DIM * HW) + hw0;
        #pragma unroll
        for (int i = 0; i < 8; ++i) {
            int idx = tid + i * NTH;
            int c = idx >> 4, n4 = (idx & 15) << 2;
            cp16(zbuf0 + c * 64 + n4, zb + (size_t)c * HW + n4);
        }
        CP_COMMIT();
    }

    int buf = 0;
    for (; tile < N_TILES; tile += GRID) {
        float* zcur = buf ? zbuf1 : zbuf0;
        float* znxt = buf ? zbuf0 : zbuf1;

        CP_WAIT0();
        __syncthreads();

        int next = tile + GRID;
        if (next < N_TILES) {
            int b = next >> 6, hw0 = (next & 63) << 6;
            const float* zb = z + (size_t)b * (C_DIM * HW) + hw0;
            #pragma unroll
            for (int i = 0; i < 8; ++i) {
                int idx = tid + i * NTH;
                int c = idx >> 4, n4 = (idx & 15) << 2;
                cp16(znxt + c * 64 + n4, zb + (size_t)c * HW + n4);
            }
            CP_COMMIT();
        }

        // ---- A_n via 4 partial fused-fma chains (argmin-invariant order) ----
        {
            int n = tid & 63, part = tid >> 6;
            const float* zp = zcur + part * 32 * 64 + n;
            float a = 0.f;
            #pragma unroll 8
            for (int c = 0; c < 32; ++c) { float v = zp[c * 64]; a = fmaf(v, v, a); }
            Ap[tid] = a;
        }
        __syncthreads();
        if (tid < 64)
            A_s[tid] = ((Ap[tid] + Ap[64 + tid]) + Ap[128 + tid]) + Ap[192 + tid];
        __syncthreads();

        // ---- mainloop: G[n,k] sequential fused-fma over c = 0..127 ----
        unsigned long long acc[8][4];
        #pragma unroll
        for (int i = 0; i < 8; ++i)
            #pragma unroll
            for (int j = 0; j < 4; ++j) acc[i][j] = 0ULL;

        #pragma unroll 4
        for (int c = 0; c < C_DIM; ++c) {
            const float2* zp = (const float2*)(zcur + c * 64) + (n0 >> 1);
            float2 p0 = zp[0], p1 = zp[1], p2 = zp[2], p3 = zp[3];  // warp-broadcast
            const ulonglong2* ep = (const ulonglong2*)(e_s + c * K_CODES + k0);
            ulonglong2 e0 = ep[0], e1 = ep[1];
            unsigned long long A8[8] = {dup2(p0.x), dup2(p0.y), dup2(p1.x), dup2(p1.y),
                                        dup2(p2.x), dup2(p2.y), dup2(p3.x), dup2(p3.y)};
            unsigned long long B4[4] = {e0.x, e0.y, e1.x, e1.y};
            #pragma unroll
            for (int i = 0; i < 8; ++i)
                #pragma unroll
                for (int j = 0; j < 4; ++j) FMA2(acc[i][j], A8[i], B4[j]);
        }

        // ---- argmin: d = RN(RN(A - 2G) + se_k), first-index tie-break ----
        #pragma unroll
        for (int i = 0; i < 8; ++i) {
            float An = A_s[n0 + i];
            unsigned long long best = 0ULL;
            #pragma unroll
            for (int j = 0; j < 4; ++j) {
                float2 g = *(float2*)&acc[i][j];
                int ka = k0 + 2 * j, kb = ka + 1;
                float da = __fadd_rn(__fadd_rn(An, -__fmul_rn(2.0f, g.x)), se_s[ka]);
                float db = __fadd_rn(__fadd_rn(An, -__fmul_rn(2.0f, g.y)), se_s[kb]);
                unsigned va = __float_as_uint(da);
                va = ((int)va < 0) ? ~va : (va | 0x80000000u);
                unsigned vb = __float_as_uint(db);
                vb = ((int)vb < 0) ? ~vb : (vb | 0x80000000u);
                unsigned long long keya = ((unsigned long long)(~va) << 32) | (unsigned)(255 - ka);
                unsigned long long keyb = ((unsigned long long)(~vb) << 32) | (unsigned)(255 - kb);
                if (keya > best) best = keya;
                if (keyb > best) best = keyb;
            }
            #pragma unroll
            for (int off = 16; off > 0; off >>= 1) {
                unsigned long long o = __shfl_xor_sync(0xFFFFFFFFu, best, off);
                if (o > best) best = o;
            }
            if (kG == 0) idx_s[n0 + i] = 255 - (int)(best & 0xFFFFFFFFull);
        }
        __syncthreads();

        // ---- epilogue: q_ste = RN(z + RN(q-z)); loss += RN(q-z)^2 ----
        {
            int b = tile >> 6, hw0 = (tile & 63) << 6;
            float* outb = out_q + (size_t)b * (C_DIM * HW) + hw0;
            #pragma unroll
            for (int i = 0; i < 8; ++i) {
                int idx = tid + i * NTH;           // 2048 float4
                int c = idx >> 4, n4 = (idx & 15) << 2;
                float4 zv = *(const float4*)(zcur + c * 64 + n4);
                int ka = idx_s[n4], kb = idx_s[n4 + 1], kc = idx_s[n4 + 2], kd = idx_s[n4 + 3];
                const float* ec = e_s + c * K_CODES;
                float d0 = ec[ka] - zv.x, d1 = ec[kb] - zv.y;
                float d2 = ec[kc] - zv.z, d3 = ec[kd] - zv.w;
                lsum_tot = fmaf(d0, d0, lsum_tot);
                lsum_tot = fmaf(d1, d1, lsum_tot);
                lsum_tot = fmaf(d2, d2, lsum_tot);
                lsum_tot = fmaf(d3, d3, lsum_tot);
                float4 o = make_float4(zv.x + d0, zv.y + d1, zv.z + d2, zv.w + d3);
                *(float4*)(outb + (size_t)c * HW + n4) = o;
            }
            if (out_idx != nullptr && tid < 64)
                out_idx[(size_t)tile * BN + tid] = (float)idx_s[tid];
        }
        buf ^= 1;
    }

    // ---- one loss reduction per block ----
    #pragma unroll
    for (int off = 16; off > 0; off >>= 1)
        lsum_tot += __shfl_xor_sync(0xFFFFFFFFu, lsum_tot, off);
    if ((tid & 31) == 0) wsum[tid >> 5] = lsum_tot;
    __syncthreads();
    if (tid == 0) {
        float t = 0.f;
        #pragma unroll
        for (int w = 0; w < 8; ++w) t += wsum[w];
        atomicAdd(&d_loss_sum, (double)t);
    }
}

__global__ void vq_finalize(float* out_s) {
    double mse = d_loss_sum * (1.0 / (double)NQ);
    out_s[0] = (float)(0.25 * mse);
    out_s[1] = (float)mse;
}

extern "C" void kernel_launch(void* const* d_in, const int* in_sizes, int n_in,
                              void* d_out, int out_size) {
    const float *z, *emb;
    if (n_in >= 2 && in_sizes[0] == K_CODES * C_DIM) {
        emb = (const float*)d_in[0];
        z   = (const float*)d_in[1];
    } else {
        z   = (const float*)d_in[0];
        emb = (const float*)d_in[1];
    }
    float* out = (float*)d_out;

    cudaFuncSetAttribute(vq_main, cudaFuncAttributeMaxDynamicSharedMemorySize,
                         SMEM_BYTES);

    float* out_idx = nullptr;
    float* out_s   = nullptr;
    long long osz = (long long)out_size;
    if (osz >= (long long)NQ + N_TOT)     out_idx = out + NQ;
    if (osz >= (long long)NQ + N_TOT + 2) out_s   = out + NQ + N_TOT;

    vq_prep<<<64, NTH>>>(emb);
    vq_main<<<GRID, NTH, SMEM_BYTES>>>(z, out, out_idx);
    if (out_s) vq_finalize<<<1, 1>>>(out_s);
}